// round 13
// baseline (speedup 1.0000x reference)
#include <cuda_runtime.h>
#include <cuda_fp16.h>
#include <math.h>
#include <stdint.h>

// Problem constants
#define BB    64      // batch
#define TT    1024    // timesteps
#define HH    256     // hidden
#define NCTA  128     // persistent CTAs (each owns 2 hidden units, both layers)
#define NT    128     // threads: tid = u*64 + b
#define CSZ   8       // cluster size
#define SLICE_BYTES 4096   // 32KB h array / 8 ranks

typedef unsigned long long ull;

// Persistent device state (static allocation only)
// h stored as fp16: [pair m][batch b][e] -> half idx = m*128 + b*2 + e
__device__ __align__(128) unsigned short g_h0[2][HH * BB];
__device__ __align__(128) unsigned short g_h1[2][HH * BB];
__device__ float    g_hmean[HH * BB];       // [j*64 + b]
__device__ float    g_xT[TT * BB];          // [t*64 + b]
__device__ unsigned g_ct;                   // global barrier counter (monotonic)

// ---------------------------------------------------------------------------
__global__ void init_kernel(const float* __restrict__ x) {
    int i = blockIdx.x * blockDim.x + threadIdx.x;
    if (i == 0) g_ct = 0u;
    if (i < TT * BB) {
        int t = i >> 6;
        int b = i & 63;
        g_xT[i] = x[b * TT + t];
    }
    if (i < HH * BB) {
        g_h0[0][i] = 0; g_h0[1][i] = 0;   // 0x0000 == +0.0 in fp16
        g_h1[0][i] = 0; g_h1[1][i] = 0;
    }
}

// ---------------------------------------------------------------------------
// helpers
// ---------------------------------------------------------------------------
__device__ __forceinline__ uint32_t smem_u32(const void* p) {
    uint32_t a;
    asm("{ .reg .u64 t; cvta.to.shared.u64 t, %1; cvt.u32.u64 %0, t; }"
        : "=r"(a) : "l"(p));
    return a;
}

__device__ __forceinline__ void fma2(ull& d, ull a, ull b) {
    asm("fma.rn.f32x2 %0, %1, %2, %0;" : "+l"(d) : "l"(a), "l"(b));
}

__device__ __forceinline__ ull pack2(float lo, float hi) {
    ull v; asm("mov.b64 %0, {%1, %2};" : "=l"(v) : "f"(lo), "f"(hi)); return v;
}

__device__ __forceinline__ float hadd2(ull v) {
    float lo, hi; asm("mov.b64 {%0, %1}, %2;" : "=f"(lo), "=f"(hi) : "l"(v));
    return lo + hi;
}

// packed half2 (as uint) -> packed f32x2 (as ull)
__device__ __forceinline__ ull h2_to_f32x2(uint32_t h2) {
    ull v;
    asm("{ .reg .b16 l, h; .reg .f32 fl, fh;\n\t"
        "mov.b32 {l, h}, %1;\n\t"
        "cvt.f32.f16 fl, l;\n\t"
        "cvt.f32.f16 fh, h;\n\t"
        "mov.b64 %0, {fl, fh}; }"
        : "=l"(v) : "r"(h2));
    return v;
}

__device__ __forceinline__ void st_h16(unsigned short* p, float f) {
    unsigned short hr = __half_as_ushort(__float2half_rn(f));
    asm volatile("st.global.cg.u16 [%0], %1;" :: "l"(p), "h"(hr) : "memory");
}

__device__ __forceinline__ void mbar_init(uint32_t a, unsigned cnt) {
    asm volatile("mbarrier.init.shared.b64 [%0], %1;" :: "r"(a), "r"(cnt) : "memory");
}

__device__ __forceinline__ void mbar_expect_tx(uint32_t a, unsigned bytes) {
    asm volatile("mbarrier.arrive.expect_tx.shared.b64 _, [%0], %1;"
                 :: "r"(a), "r"(bytes) : "memory");
}

__device__ __forceinline__ void mbar_wait(uint32_t a, unsigned parity) {
    asm volatile(
        "{\n\t.reg .pred P;\n\t"
        "WL%=:\n\t"
        "mbarrier.try_wait.parity.acquire.cta.shared::cta.b64 P, [%0], %1, 0x989680;\n\t"
        "@P bra.uni WD%=;\n\t"
        "bra.uni WL%=;\n\t"
        "WD%=:\n\t}"
        :: "r"(a), "r"(parity) : "memory");
}

// Multicast bulk copy: deliver [src, src+bytes) to the same smem offset in
// every CTA of the cluster whose bit is set in mask; complete_tx lands on the
// same-offset mbar in each receiving CTA.
__device__ __forceinline__ void bulk_g2s_mc(uint32_t dst, const void* src,
                                            unsigned bytes, uint32_t mbar,
                                            unsigned short mask) {
    asm volatile(
        "cp.async.bulk.shared::cluster.global.mbarrier::complete_tx::bytes"
        ".multicast::cluster [%0], [%1], %2, [%3], %4;"
        :: "r"(dst), "l"(src), "r"(bytes), "r"(mbar), "h"(mask) : "memory");
}

__device__ __forceinline__ float sigm(float x) {
    return __fdividef(1.f, 1.f + __expf(-x));
}
__device__ __forceinline__ float tanh_f(float x) {
    float e = __expf(-2.f * fabsf(x));
    float t = __fdividef(1.f - e, 1.f + e);
    return copysignf(t, x);
}

// ---------------------------------------------------------------------------
// Persistent fused 2-layer LSTM — fp16 h exchange + cluster-8 TMA multicast.
// Slot t: layer0 computes step t (t<TT); layer1 computes step t-1 (t>0).
//
// Global barrier identical to the proven R2/R12 kernel. h broadcast is now
// cooperative: cluster rank r loads ONLY its 4KB slice of each h array and
// multicasts it to all 8 CTAs' smem (chip L2 reads: 8.4MB -> 1.05MB/slot).
// One mbar per CTA accumulates 16 partial complete_tx (8 ranks x 2 arrays).
// ---------------------------------------------------------------------------
__global__ void __launch_bounds__(NT, 1) __cluster_dims__(CSZ, 1, 1)
lstm_persistent(
    const float* __restrict__ Wh0, const float* __restrict__ Wx0,
    const float* __restrict__ b0,
    const float* __restrict__ Wx1, const float* __restrict__ Wh1,
    const float* __restrict__ b1)
{
    extern __shared__ char smem[];
    // bytes: sh0[32768] | sh1[32768] | w0[8192] | wx[8192] | w1[8192] | mbar
    float* w0s = (float*)(smem + 65536);
    float* wxs = (float*)(smem + 65536 + 8192);
    float* w1s = (float*)(smem + 65536 + 16384);

    const uint32_t sbase   = smem_u32(smem);
    const uint32_t sh1_u32 = sbase + 32768;
    const uint32_t mbar_u  = sbase + 90112;

    const int tid = threadIdx.x;
    const int b   = tid & 63;
    const int u   = tid >> 6;
    const int j   = blockIdx.x * 2 + u;

    uint32_t rank;
    asm("mov.u32 %0, %%cluster_ctarank;" : "=r"(rank));

    if (tid == 0) mbar_init(mbar_u, 1);

    // Preload weight slices as k-pair float2 per gate:
    // w[(m*2+u)*4 + g] = { W[2m][g*256+j], W[2m+1][g*256+j] }
    for (int idx = tid; idx < 256; idx += NT) {
        const int m  = idx >> 1;
        const int uu = idx & 1;
        const int jj = blockIdx.x * 2 + uu;
        float2* d0 = (float2*)w0s + idx * 4;
        float2* dx = (float2*)wxs + idx * 4;
        float2* d1 = (float2*)w1s + idx * 4;
        const float* ra0 = Wh0 + (2 * m) * 1024;
        const float* rb0 = Wh0 + (2 * m + 1) * 1024;
        const float* rax = Wx1 + (2 * m) * 1024;
        const float* rbx = Wx1 + (2 * m + 1) * 1024;
        const float* ra1 = Wh1 + (2 * m) * 1024;
        const float* rb1 = Wh1 + (2 * m + 1) * 1024;
        #pragma unroll
        for (int g = 0; g < 4; ++g) {
            d0[g] = make_float2(ra0[g * 256 + jj], rb0[g * 256 + jj]);
            dx[g] = make_float2(rax[g * 256 + jj], rbx[g * 256 + jj]);
            d1[g] = make_float2(ra1[g * 256 + jj], rb1[g * 256 + jj]);
        }
    }
    const float4 bia0 = make_float4(b0[j], b0[256 + j], b0[512 + j], b0[768 + j]);
    const float4 bia1 = make_float4(b1[j], b1[256 + j], b1[512 + j], b1[768 + j]);
    const float4 wx0  = make_float4(Wx0[j], Wx0[256 + j], Wx0[512 + j], Wx0[768 + j]);

    float c0 = 0.f, c1 = 0.f, hsum = 0.f;
    __syncthreads();   // mbar init + weights visible (CTA scope)

    // Cluster barrier: all 8 CTAs' mbars must be initialized before any
    // peer multicast can deliver complete_tx into them.
    asm volatile("barrier.cluster.arrive.aligned;" ::: "memory");
    asm volatile("barrier.cluster.wait.aligned;"   ::: "memory");

    // per-thread pointers: half2 pair (m,b) at pX[m*64] (uint view)
    const uint32_t* ph0 = (const uint32_t*)smem + b;
    const uint32_t* ph1 = (const uint32_t*)(smem + 32768) + b;
    const ulonglong2* pw0 = (const ulonglong2*)w0s + u * 2;   // [m*4], [m*4+1]
    const ulonglong2* pwx = (const ulonglong2*)wxs + u * 2;
    const ulonglong2* pw1 = (const ulonglong2*)w1s + u * 2;

    const int houti = (j >> 1) * 128 + b * 2 + (j & 1);

    for (int t = 0; t <= TT; ++t) {
        if (t > 0) {
            __threadfence();      // own h stores -> L2 (parallel across threads)
            __syncthreads();      // whole CTA done with previous slot
            if (tid == 0) {
                atomicAdd(&g_ct, 1u);
                const unsigned target = (unsigned)t * NCTA;
                while (*((volatile unsigned*)&g_ct) < target) { }
            }
            // NOTE: no __syncthreads here — other threads run ahead to the
            // mbar wait, which gates on this slot's multicast completions.
        }

        if (tid == 0) {
            asm volatile("fence.proxy.async;" ::: "memory");
            // cooperative slices: rank r loads bytes [r*4K, (r+1)*4K) of each
            // h array and multicasts to all 8 CTAs of the cluster.
            const char* s0 = (const char*)g_h0[(t + 1) & 1] + rank * SLICE_BYTES;
            const char* s1 = (const char*)g_h1[t & 1]       + rank * SLICE_BYTES;
            mbar_expect_tx(mbar_u, 65536);   // 8 ranks x (4K + 4K)
            bulk_g2s_mc(sbase   + rank * SLICE_BYTES, s0, SLICE_BYTES, mbar_u, 0xFF);
            bulk_g2s_mc(sh1_u32 + rank * SLICE_BYTES, s1, SLICE_BYTES, mbar_u, 0xFF);
        }

        // init gate accumulators (lane-lo gets bias + x-contribution)
        const float xv = (t < TT) ? g_xT[t * BB + b] : 0.f;
        ull a0i = pack2(fmaf(xv, wx0.x, bia0.x), 0.f);
        ull a0f = pack2(fmaf(xv, wx0.y, bia0.y), 0.f);
        ull a0g = pack2(fmaf(xv, wx0.z, bia0.z), 0.f);
        ull a0o = pack2(fmaf(xv, wx0.w, bia0.w), 0.f);
        ull a1i = pack2(bia1.x, 0.f);
        ull a1f = pack2(bia1.y, 0.f);
        ull a1g = pack2(bia1.z, 0.f);
        ull a1o = pack2(bia1.w, 0.f);

        mbar_wait(mbar_u, (unsigned)(t & 1));

        #pragma unroll 8
        for (int m = 0; m < 128; ++m) {
            const ull hv2  = h2_to_f32x2(ph0[m * 64]);
            const ull h1v2 = h2_to_f32x2(ph1[m * 64]);
            const ulonglong2 w0a = pw0[m * 4];
            const ulonglong2 w0b = pw0[m * 4 + 1];
            fma2(a0i, hv2, w0a.x); fma2(a0f, hv2, w0a.y);
            fma2(a0g, hv2, w0b.x); fma2(a0o, hv2, w0b.y);
            const ulonglong2 wxa = pwx[m * 4];
            const ulonglong2 wxb = pwx[m * 4 + 1];
            fma2(a1i, hv2, wxa.x); fma2(a1f, hv2, wxa.y);
            fma2(a1g, hv2, wxb.x); fma2(a1o, hv2, wxb.y);
            const ulonglong2 w1a = pw1[m * 4];
            const ulonglong2 w1b = pw1[m * 4 + 1];
            fma2(a1i, h1v2, w1a.x); fma2(a1f, h1v2, w1a.y);
            fma2(a1g, h1v2, w1b.x); fma2(a1o, h1v2, w1b.y);
        }

        if (t < TT) {   // layer0 step t
            const float ig = sigm(hadd2(a0i));
            const float fg = sigm(hadd2(a0f));
            const float gg = tanh_f(hadd2(a0g));
            const float og = sigm(hadd2(a0o));
            c0 = fmaf(fg, c0, ig * gg);
            const float h0n = og * tanh_f(c0);
            st_h16(&g_h0[t & 1][houti], h0n);
        }
        if (t > 0) {    // layer1 step t-1
            const float ig = sigm(hadd2(a1i));
            const float fg = sigm(hadd2(a1f));
            const float gg = tanh_f(hadd2(a1g));
            const float og = sigm(hadd2(a1o));
            c1 = fmaf(fg, c1, ig * gg);
            const float h1n = og * tanh_f(c1);
            hsum += h1n;
            if (t < TT) st_h16(&g_h1[(t + 1) & 1][houti], h1n);
        }
    }

    g_hmean[j * 64 + b] = hsum * (1.f / 1024.f);

    // No CTA may exit while a peer's multicast targeting its smem could be
    // in flight.
    __syncthreads();
    asm volatile("barrier.cluster.arrive.aligned;" ::: "memory");
    asm volatile("barrier.cluster.wait.aligned;"   ::: "memory");
}

// ---------------------------------------------------------------------------
// Head: theta projection, concat, 3x (dense + ELU), final dense. Runs once.
// ---------------------------------------------------------------------------
__global__ void final_kernel(
    const float* __restrict__ theta,
    const float* __restrict__ pW, const float* __restrict__ pb,
    const float* __restrict__ l0W, const float* __restrict__ l0b,
    const float* __restrict__ l1W, const float* __restrict__ l1b,
    const float* __restrict__ l2W, const float* __restrict__ l2b,
    const float* __restrict__ oW,  const float* __restrict__ ob,
    float* __restrict__ out)
{
    __shared__ float hin[512];
    __shared__ float act0[256];
    __shared__ float act1[256];
    __shared__ float act2[128];
    const int bb = blockIdx.x;
    const int tj = threadIdx.x;

    hin[tj] = g_hmean[tj * 64 + bb];
    {
        float s = pb[tj];
        #pragma unroll
        for (int d = 0; d < 5; ++d) s = fmaf(theta[bb * 5 + d], pW[d * 256 + tj], s);
        hin[256 + tj] = s;
    }
    __syncthreads();
    {
        float acc = l0b[tj];
        for (int k = 0; k < 512; ++k) acc = fmaf(hin[k], l0W[k * 256 + tj], acc);
        act0[tj] = acc > 0.f ? acc : expm1f(acc);
    }
    __syncthreads();
    {
        float acc = l1b[tj];
        for (int k = 0; k < 256; ++k) acc = fmaf(act0[k], l1W[k * 256 + tj], acc);
        act1[tj] = acc > 0.f ? acc : expm1f(acc);
    }
    __syncthreads();
    if (tj < 128) {
        float acc = l2b[tj];
        for (int k = 0; k < 256; ++k) acc = fmaf(act1[k], l2W[k * 128 + tj], acc);
        act2[tj] = acc > 0.f ? acc : expm1f(acc);
    }
    __syncthreads();
    if (tj == 0) {
        float s = ob[0];
        for (int k = 0; k < 128; ++k) s = fmaf(act2[k], oW[k], s);
        out[bb] = s;
    }
}

// ---------------------------------------------------------------------------
extern "C" void kernel_launch(void* const* d_in, const int* in_sizes, int n_in,
                              void* d_out, int out_size) {
    const float* x     = (const float*)d_in[0];
    const float* theta = (const float*)d_in[1];
    const float* Wx0   = (const float*)d_in[2];
    const float* Wh0   = (const float*)d_in[3];
    const float* b0    = (const float*)d_in[4];
    const float* Wx1   = (const float*)d_in[5];
    const float* Wh1   = (const float*)d_in[6];
    const float* b1    = (const float*)d_in[7];
    const float* pW    = (const float*)d_in[8];
    const float* pb    = (const float*)d_in[9];
    const float* l0W   = (const float*)d_in[10];
    const float* l0b   = (const float*)d_in[11];
    const float* l1W   = (const float*)d_in[12];
    const float* l1b   = (const float*)d_in[13];
    const float* l2W   = (const float*)d_in[14];
    const float* l2b   = (const float*)d_in[15];
    const float* oW    = (const float*)d_in[16];
    const float* ob    = (const float*)d_in[17];

    // 32K + 32K staging + 3*8K weights + mbar = 90112 + 64 bytes
    const int smem_bytes = 90176;
    cudaFuncSetAttribute(lstm_persistent,
                         cudaFuncAttributeMaxDynamicSharedMemorySize, smem_bytes);

    init_kernel<<<(TT * BB + 255) / 256, 256>>>(x);
    lstm_persistent<<<NCTA, NT, smem_bytes>>>(Wh0, Wx0, b0, Wx1, Wh1, b1);
    final_kernel<<<BB, 256>>>(theta, pW, pb, l0W, l0b, l1W, l1b,
                              l2W, l2b, oW, ob, (float*)d_out);
}

// round 14
// speedup vs baseline: 1.3984x; 1.3984x over previous
#include <cuda_runtime.h>
#include <cuda_fp16.h>
#include <math.h>
#include <stdint.h>

// Problem constants
#define BB    64      // batch
#define TT    1024    // timesteps
#define HH    256     // hidden
#define NCTA  128     // persistent CTAs (each owns 2 hidden units, both layers)
#define NT    160     // 4 compute warps (tid 0..127) + 1 producer warp

typedef unsigned long long ull;

// Persistent device state (static allocation only)
// h0 fp32: [pair m][batch b][e] -> float idx = m*128 + b*2 + e
// h1 fp16: same index into ushort array
__device__ __align__(128) float          g_h0[2][HH * BB];
__device__ __align__(128) unsigned short g_h1[2][HH * BB];
__device__ float    g_hmean[HH * BB];       // [j*64 + b]
__device__ float    g_xT[TT * BB];          // [t*64 + b]
__device__ __align__(128) unsigned g_A;     // h0-ready arrivals (mid-slot)
__device__ __align__(128) unsigned g_B;     // h1-ready arrivals (end-of-slot)

// smem layout (bytes)
#define SH0_OFF   0        // sh0[2]: 2 x 65536 (fp32 h0 stage)
#define SH1_OFF   131072   // sh1[2]: 2 x 32768 (fp16 h1 stage)
#define W0_OFF    196608
#define WX_OFF    204800
#define W1_OFF    212992
#define MB_OFF    221184   // full0[2] | full1[2] | empty0[2] | empty1[2]
#define SMEM_SZ   221248

// ---------------------------------------------------------------------------
__global__ void init_kernel(const float* __restrict__ x) {
    int i = blockIdx.x * blockDim.x + threadIdx.x;
    if (i == 0) { g_A = 0u; g_B = 0u; }
    if (i < TT * BB) {
        int t = i >> 6;
        int b = i & 63;
        g_xT[i] = x[b * TT + t];
    }
}

// ---------------------------------------------------------------------------
// helpers
// ---------------------------------------------------------------------------
__device__ __forceinline__ uint32_t smem_u32(const void* p) {
    uint32_t a;
    asm("{ .reg .u64 t; cvta.to.shared.u64 t, %1; cvt.u32.u64 %0, t; }"
        : "=r"(a) : "l"(p));
    return a;
}

__device__ __forceinline__ void fma2(ull& d, ull a, ull b) {
    asm("fma.rn.f32x2 %0, %1, %2, %0;" : "+l"(d) : "l"(a), "l"(b));
}

__device__ __forceinline__ ull pack2(float lo, float hi) {
    ull v; asm("mov.b64 %0, {%1, %2};" : "=l"(v) : "f"(lo), "f"(hi)); return v;
}

__device__ __forceinline__ float hadd2(ull v) {
    float lo, hi; asm("mov.b64 {%0, %1}, %2;" : "=f"(lo), "=f"(hi) : "l"(v));
    return lo + hi;
}

// packed half2 (as uint) -> packed f32x2 (as ull)
__device__ __forceinline__ ull h2_to_f32x2(uint32_t h2) {
    ull v;
    asm("{ .reg .b16 l, h; .reg .f32 fl, fh;\n\t"
        "mov.b32 {l, h}, %1;\n\t"
        "cvt.f32.f16 fl, l;\n\t"
        "cvt.f32.f16 fh, h;\n\t"
        "mov.b64 %0, {fl, fh}; }"
        : "=l"(v) : "r"(h2));
    return v;
}

__device__ __forceinline__ void st_h16(unsigned short* p, float f) {
    unsigned short hr = __half_as_ushort(__float2half_rn(f));
    asm volatile("st.global.cg.u16 [%0], %1;" :: "l"(p), "h"(hr) : "memory");
}

__device__ __forceinline__ void mbar_init(uint32_t a, unsigned cnt) {
    asm volatile("mbarrier.init.shared.b64 [%0], %1;" :: "r"(a), "r"(cnt) : "memory");
}

__device__ __forceinline__ void mbar_expect_tx(uint32_t a, unsigned bytes) {
    asm volatile("mbarrier.arrive.expect_tx.shared.b64 _, [%0], %1;"
                 :: "r"(a), "r"(bytes) : "memory");
}

__device__ __forceinline__ void mbar_arrive(uint32_t a) {
    asm volatile("mbarrier.arrive.shared.b64 _, [%0];" :: "r"(a) : "memory");
}

__device__ __forceinline__ void mbar_wait(uint32_t a, unsigned parity) {
    asm volatile(
        "{\n\t.reg .pred P;\n\t"
        "WL%=:\n\t"
        "mbarrier.try_wait.parity.acquire.cta.shared::cta.b64 P, [%0], %1, 0x989680;\n\t"
        "@P bra.uni WD%=;\n\t"
        "bra.uni WL%=;\n\t"
        "WD%=:\n\t}"
        :: "r"(a), "r"(parity) : "memory");
}

__device__ __forceinline__ void bulk_g2s(uint32_t dst, const void* src,
                                         unsigned bytes, uint32_t mbar) {
    asm volatile(
        "cp.async.bulk.shared::cluster.global.mbarrier::complete_tx::bytes "
        "[%0], [%1], %2, [%3];"
        :: "r"(dst), "l"(src), "r"(bytes), "r"(mbar) : "memory");
}

__device__ __forceinline__ float sigm(float x) {
    return __fdividef(1.f, 1.f + __expf(-x));
}
__device__ __forceinline__ float tanh_f(float x) {
    float e = __expf(-2.f * fabsf(x));
    float t = __fdividef(1.f - e, 1.f + e);
    return copysignf(t, x);
}

// ---------------------------------------------------------------------------
// Persistent fused 2-layer LSTM — split barriers + producer-warp prefetch.
//
// Slot t: phase0 = layer0 step t (a0: needs h0(t-1));
//         phase1 = layer1 step t-1 (a1: needs h0(t-1) + h1(t-2)).
// Barrier A (+128/slot) announces h0(t) mid-slot; B announces h1 end-of-slot.
// Producer warp (tid 128) prefetches slot t's stages DURING slot t-1:
//   wait empty (stage reuse safe) -> poll A/B -> TMA into double-buffered smem.
// Compute warps never poll globals; they wait only on local full-mbars.
// ---------------------------------------------------------------------------
__global__ void __launch_bounds__(NT, 1) lstm_persistent(
    const float* __restrict__ Wh0, const float* __restrict__ Wx0,
    const float* __restrict__ b0,
    const float* __restrict__ Wx1, const float* __restrict__ Wh1,
    const float* __restrict__ b1)
{
    extern __shared__ char smem[];
    float* w0s = (float*)(smem + W0_OFF);
    float* wxs = (float*)(smem + WX_OFF);
    float* w1s = (float*)(smem + W1_OFF);

    const uint32_t sbase = smem_u32(smem);
    const uint32_t mb    = sbase + MB_OFF;
    // full0[b]=mb+b*8, full1[b]=mb+16+b*8, empty0[b]=mb+32+b*8, empty1[b]=mb+48+b*8

    const int tid = threadIdx.x;
    const bool isComp = tid < 128;
    const int b = tid & 63;
    const int u = (tid >> 6) & 1;
    const int j = blockIdx.x * 2 + u;

    if (tid == 0) {
        #pragma unroll
        for (int i = 0; i < 4; ++i) { mbar_init(mb + i * 8, 1); }        // full0/full1
        #pragma unroll
        for (int i = 4; i < 8; ++i) { mbar_init(mb + i * 8, 1); }        // empty0/empty1
    }

    // zero pre-armed stages: sh0[0] (h0(-1)=0), sh1[0] and sh1[1] (h1(-1),h1(-2)=0)
    for (int i = tid; i < 16384; i += NT) ((float*)smem)[i] = 0.f;
    for (int i = tid; i < 32768; i += NT)
        ((unsigned short*)(smem + SH1_OFF))[i] = 0;

    // weight slices: w[(m*2+u)*4+g] = { W[2m][g*256+j], W[2m+1][g*256+j] }
    for (int idx = tid; idx < 256; idx += NT) {
        const int m  = idx >> 1;
        const int uu = idx & 1;
        const int jj = blockIdx.x * 2 + uu;
        float2* d0 = (float2*)w0s + idx * 4;
        float2* dx = (float2*)wxs + idx * 4;
        float2* d1 = (float2*)w1s + idx * 4;
        const float* ra0 = Wh0 + (2 * m) * 1024;
        const float* rb0 = Wh0 + (2 * m + 1) * 1024;
        const float* rax = Wx1 + (2 * m) * 1024;
        const float* rbx = Wx1 + (2 * m + 1) * 1024;
        const float* ra1 = Wh1 + (2 * m) * 1024;
        const float* rb1 = Wh1 + (2 * m + 1) * 1024;
        #pragma unroll
        for (int g = 0; g < 4; ++g) {
            d0[g] = make_float2(ra0[g * 256 + jj], rb0[g * 256 + jj]);
            dx[g] = make_float2(rax[g * 256 + jj], rbx[g * 256 + jj]);
            d1[g] = make_float2(ra1[g * 256 + jj], rb1[g * 256 + jj]);
        }
    }

    float4 bia0 = make_float4(0.f, 0.f, 0.f, 0.f);
    float4 bia1 = bia0, wx0 = bia0;
    if (isComp) {
        bia0 = make_float4(b0[j], b0[256 + j], b0[512 + j], b0[768 + j]);
        bia1 = make_float4(b1[j], b1[256 + j], b1[512 + j], b1[768 + j]);
        wx0  = make_float4(Wx0[j], Wx0[256 + j], Wx0[512 + j], Wx0[768 + j]);
    }

    __syncthreads();   // mbars, zeroed stages, weights visible to all 5 warps

    if (isComp) {
        // ------------------------- compute warps -------------------------
        const ulonglong2* pw0 = (const ulonglong2*)w0s + u * 2;
        const ulonglong2* pwx = (const ulonglong2*)wxs + u * 2;
        const ulonglong2* pw1 = (const ulonglong2*)w1s + u * 2;
        const int houti = (j >> 1) * 128 + b * 2 + (j & 1);

        float c0 = 0.f, c1 = 0.f, hsum = 0.f;
        unsigned f0p0 = 0, f0p1 = 0, f1p0 = 0, f1p1 = 0;

        for (int t = 0; t <= TT; ++t) {
            const int p = t & 1;
            const ull* ph0 = (const ull*)(smem + (p ? 65536 : 0)) + b;

            // ---- phase 0: layer0 (needs h0(t-1)) ----
            if (t > 0) {
                unsigned ph = p ? f0p1 : f0p0;
                mbar_wait(mb + p * 8, ph);
                if (p) f0p1 ^= 1; else f0p0 ^= 1;
            }

            const float xv = (t < TT) ? g_xT[t * BB + b] : 0.f;
            ull a0i = pack2(fmaf(xv, wx0.x, bia0.x), 0.f);
            ull a0f = pack2(fmaf(xv, wx0.y, bia0.y), 0.f);
            ull a0g = pack2(fmaf(xv, wx0.z, bia0.z), 0.f);
            ull a0o = pack2(fmaf(xv, wx0.w, bia0.w), 0.f);
            #pragma unroll 8
            for (int m = 0; m < 128; ++m) {
                const ull hv2 = ph0[m * 64];
                const ulonglong2 w0a = pw0[m * 4];
                const ulonglong2 w0b = pw0[m * 4 + 1];
                fma2(a0i, hv2, w0a.x); fma2(a0f, hv2, w0a.y);
                fma2(a0g, hv2, w0b.x); fma2(a0o, hv2, w0b.y);
            }
            if (t < TT) {
                const float ig = sigm(hadd2(a0i));
                const float fg = sigm(hadd2(a0f));
                const float gg = tanh_f(hadd2(a0g));
                const float og = sigm(hadd2(a0o));
                c0 = fmaf(fg, c0, ig * gg);
                __stcg(&g_h0[p][houti], og * tanh_f(c0));
            }
            __threadfence();
            asm volatile("bar.sync 1, 128;" ::: "memory");
            if (tid == 0) atomicAdd(&g_A, 1u);            // h0(t) announced

            // ---- phase 1: layer1 step t-1 (needs h0(t-1) + h1(t-2)) ----
            if (t > 1) {
                unsigned ph = p ? f1p1 : f1p0;
                mbar_wait(mb + 16 + p * 8, ph);
                if (p) f1p1 ^= 1; else f1p0 ^= 1;
            }
            const uint32_t* ph1 = (const uint32_t*)(smem + SH1_OFF + p * 32768) + b;
            ull a1i = pack2(bia1.x, 0.f);
            ull a1f = pack2(bia1.y, 0.f);
            ull a1g = pack2(bia1.z, 0.f);
            ull a1o = pack2(bia1.w, 0.f);
            #pragma unroll 8
            for (int m = 0; m < 128; ++m) {
                const ull hv2  = ph0[m * 64];
                const ull h1v2 = h2_to_f32x2(ph1[m * 64]);
                const ulonglong2 wxa = pwx[m * 4];
                const ulonglong2 wxb = pwx[m * 4 + 1];
                fma2(a1i, hv2, wxa.x); fma2(a1f, hv2, wxa.y);
                fma2(a1g, hv2, wxb.x); fma2(a1o, hv2, wxb.y);
                const ulonglong2 w1a = pw1[m * 4];
                const ulonglong2 w1b = pw1[m * 4 + 1];
                fma2(a1i, h1v2, w1a.x); fma2(a1f, h1v2, w1a.y);
                fma2(a1g, h1v2, w1b.x); fma2(a1o, h1v2, w1b.y);
            }
            if (t > 0) {
                const float ig = sigm(hadd2(a1i));
                const float fg = sigm(hadd2(a1f));
                const float gg = tanh_f(hadd2(a1g));
                const float og = sigm(hadd2(a1o));
                c1 = fmaf(fg, c1, ig * gg);
                const float h1n = og * tanh_f(c1);
                hsum += h1n;
                if (t < TT) st_h16(&g_h1[(t + 1) & 1][houti], h1n);
            }
            __threadfence();
            asm volatile("bar.sync 1, 128;" ::: "memory");
            if (tid == 0) {
                atomicAdd(&g_B, 1u);                      // h1(t-1) announced
                mbar_arrive(mb + 32 + p * 8);             // sh0[p] consumed
                mbar_arrive(mb + 48 + p * 8);             // sh1[p] consumed
            }
        }
        g_hmean[j * 64 + b] = hsum * (1.f / 1024.f);

    } else if (tid == 128) {
        // ------------------------- producer warp -------------------------
        unsigned e0p0 = 0, e0p1 = 0, e1p0 = 0, e1p1 = 0;
        for (int t = 1; t <= TT; ++t) {
            const int p = t & 1;
            // h0 stage for slot t  (reads h0(t-1) at parity (t-1)&1)
            if (t >= 2) {
                unsigned ph = p ? e0p1 : e0p0;
                mbar_wait(mb + 32 + p * 8, ph);
                if (p) e0p1 ^= 1; else e0p0 ^= 1;
            }
            while (*((volatile unsigned*)&g_A) < 128u * (unsigned)t) { }
            asm volatile("fence.proxy.async;" ::: "memory");
            mbar_expect_tx(mb + p * 8, 65536);
            bulk_g2s(sbase + p * 65536, g_h0[(t - 1) & 1], 65536, mb + p * 8);

            // h1 stage for slot t  (reads h1(t-2) at parity t&1)
            if (t >= 2) {
                unsigned ph = p ? e1p1 : e1p0;
                mbar_wait(mb + 48 + p * 8, ph);
                if (p) e1p1 ^= 1; else e1p0 ^= 1;
                while (*((volatile unsigned*)&g_B) < 128u * (unsigned)t) { }
                asm volatile("fence.proxy.async;" ::: "memory");
                mbar_expect_tx(mb + 16 + p * 8, 32768);
                bulk_g2s(sbase + SH1_OFF + p * 32768, g_h1[p], 32768,
                         mb + 16 + p * 8);
            }
        }
    }
}

// ---------------------------------------------------------------------------
// Head: theta projection, concat, 3x (dense + ELU), final dense. Runs once.
// ---------------------------------------------------------------------------
__global__ void final_kernel(
    const float* __restrict__ theta,
    const float* __restrict__ pW, const float* __restrict__ pb,
    const float* __restrict__ l0W, const float* __restrict__ l0b,
    const float* __restrict__ l1W, const float* __restrict__ l1b,
    const float* __restrict__ l2W, const float* __restrict__ l2b,
    const float* __restrict__ oW,  const float* __restrict__ ob,
    float* __restrict__ out)
{
    __shared__ float hin[512];
    __shared__ float act0[256];
    __shared__ float act1[256];
    __shared__ float act2[128];
    const int bb = blockIdx.x;
    const int tj = threadIdx.x;

    hin[tj] = g_hmean[tj * 64 + bb];
    {
        float s = pb[tj];
        #pragma unroll
        for (int d = 0; d < 5; ++d) s = fmaf(theta[bb * 5 + d], pW[d * 256 + tj], s);
        hin[256 + tj] = s;
    }
    __syncthreads();
    {
        float acc = l0b[tj];
        for (int k = 0; k < 512; ++k) acc = fmaf(hin[k], l0W[k * 256 + tj], acc);
        act0[tj] = acc > 0.f ? acc : expm1f(acc);
    }
    __syncthreads();
    {
        float acc = l1b[tj];
        for (int k = 0; k < 256; ++k) acc = fmaf(act0[k], l1W[k * 256 + tj], acc);
        act1[tj] = acc > 0.f ? acc : expm1f(acc);
    }
    __syncthreads();
    if (tj < 128) {
        float acc = l2b[tj];
        for (int k = 0; k < 256; ++k) acc = fmaf(act1[k], l2W[k * 128 + tj], acc);
        act2[tj] = acc > 0.f ? acc : expm1f(acc);
    }
    __syncthreads();
    if (tj == 0) {
        float s = ob[0];
        for (int k = 0; k < 128; ++k) s = fmaf(act2[k], oW[k], s);
        out[bb] = s;
    }
}

// ---------------------------------------------------------------------------
extern "C" void kernel_launch(void* const* d_in, const int* in_sizes, int n_in,
                              void* d_out, int out_size) {
    const float* x     = (const float*)d_in[0];
    const float* theta = (const float*)d_in[1];
    const float* Wx0   = (const float*)d_in[2];
    const float* Wh0   = (const float*)d_in[3];
    const float* b0    = (const float*)d_in[4];
    const float* Wx1   = (const float*)d_in[5];
    const float* Wh1   = (const float*)d_in[6];
    const float* b1    = (const float*)d_in[7];
    const float* pW    = (const float*)d_in[8];
    const float* pb    = (const float*)d_in[9];
    const float* l0W   = (const float*)d_in[10];
    const float* l0b   = (const float*)d_in[11];
    const float* l1W   = (const float*)d_in[12];
    const float* l1b   = (const float*)d_in[13];
    const float* l2W   = (const float*)d_in[14];
    const float* l2b   = (const float*)d_in[15];
    const float* oW    = (const float*)d_in[16];
    const float* ob    = (const float*)d_in[17];

    cudaFuncSetAttribute(lstm_persistent,
                         cudaFuncAttributeMaxDynamicSharedMemorySize, SMEM_SZ);

    init_kernel<<<(TT * BB + 255) / 256, 256>>>(x);
    lstm_persistent<<<NCTA, NT, SMEM_SZ>>>(Wh0, Wx0, b0, Wx1, Wh1, b1);
    final_kernel<<<BB, 256>>>(theta, pW, pb, l0W, l0b, l1W, l1b,
                              l2W, l2b, oW, ob, (float*)d_out);
}